// round 2
// baseline (speedup 1.0000x reference)
#include <cuda_runtime.h>
#include <cuda_bf16.h>
#include <math.h>

// Problem constants
#define BB 16
#define QQ 100
#define EE 256
#define HH 8
#define HD 32
#define SS 4096
#define NEGBIG (-1e9f)

// Scratch (device globals: allocation-free rule)
__device__ float g_imgT[(size_t)BB * SS * EE];   // (B*S, E) row-major
__device__ float g_K[(size_t)BB * SS * EE];
__device__ float g_V[(size_t)BB * SS * EE];
__device__ float g_Qp[(size_t)BB * QQ * EE];
__device__ float g_attn[(size_t)BB * QQ * EE];

#define SPLIT 4
#define NPART (BB * HH * SPLIT * QQ)             // 51200
__device__ float g_Pm[NPART];
__device__ float g_Pl[NPART];
__device__ float g_Pacc[(size_t)NPART * HD];

// ---------------------------------------------------------------------------
// Transpose image_features (B, E, S) -> g_imgT (B*S, E)
// ---------------------------------------------------------------------------
__global__ void transpose_img(const float* __restrict__ img) {
    __shared__ float tile[32][33];
    int b = blockIdx.z;
    int e0 = blockIdx.y * 32;
    int s0 = blockIdx.x * 32;
    int tx = threadIdx.x, ty = threadIdx.y;  // 32 x 8
    const float* ip = img + ((size_t)b * EE + e0) * SS + s0;
    #pragma unroll
    for (int i = ty; i < 32; i += 8)
        tile[i][tx] = ip[(size_t)i * SS + tx];          // tile[e][s]
    __syncthreads();
    float* op = g_imgT + ((size_t)b * SS + s0) * EE + e0;
    #pragma unroll
    for (int i = ty; i < 32; i += 8)
        op[(size_t)i * EE + tx] = tile[tx][i];          // out[s][e]
}

// ---------------------------------------------------------------------------
// C[r,n] = sum_c (A1[r,c] (+A2[r,c])) * W[n,c] + bias[n]
// K == N == 256. BM=128, BN=64, BK=16, 256 threads, 8x4 microtile.
// ---------------------------------------------------------------------------
#define GBM 128
#define GBN 64
#define GBK 16
__global__ __launch_bounds__(256)
void sgemm_nt(const float* __restrict__ A1, const float* __restrict__ A2,
              const float* __restrict__ W, const float* __restrict__ bias,
              float* __restrict__ C, int M) {
    __shared__ float As[GBK][GBM + 4];
    __shared__ float Bs[GBK][GBN + 4];
    int bm = blockIdx.x * GBM;
    int bn = blockIdx.y * GBN;
    int tid = threadIdx.x;
    int tx = tid % 16, ty = tid / 16;
    float acc[8][4];
    #pragma unroll
    for (int i = 0; i < 8; i++)
        #pragma unroll
        for (int j = 0; j < 4; j++) acc[i][j] = 0.f;

    int a_row = tid >> 2;          // 0..63
    int a_c4  = (tid & 3) * 4;     // 0,4,8,12

    for (int k0 = 0; k0 < EE; k0 += GBK) {
        #pragma unroll
        for (int rr = 0; rr < GBM; rr += 64) {
            int row = bm + a_row + rr;
            float4 av = make_float4(0.f, 0.f, 0.f, 0.f);
            if (row < M) {
                av = *(const float4*)(A1 + (size_t)row * EE + k0 + a_c4);
                if (A2) {
                    float4 p = *(const float4*)(A2 + (size_t)row * EE + k0 + a_c4);
                    av.x += p.x; av.y += p.y; av.z += p.z; av.w += p.w;
                }
            }
            As[a_c4 + 0][a_row + rr] = av.x;
            As[a_c4 + 1][a_row + rr] = av.y;
            As[a_c4 + 2][a_row + rr] = av.z;
            As[a_c4 + 3][a_row + rr] = av.w;
        }
        {
            float4 wv = *(const float4*)(W + (size_t)(bn + a_row) * EE + k0 + a_c4);
            Bs[a_c4 + 0][a_row] = wv.x;
            Bs[a_c4 + 1][a_row] = wv.y;
            Bs[a_c4 + 2][a_row] = wv.z;
            Bs[a_c4 + 3][a_row] = wv.w;
        }
        __syncthreads();
        #pragma unroll
        for (int k = 0; k < GBK; k++) {
            float af[8], bf[4];
            float4 a0 = *(const float4*)&As[k][ty * 8];
            float4 a1 = *(const float4*)&As[k][ty * 8 + 4];
            af[0]=a0.x; af[1]=a0.y; af[2]=a0.z; af[3]=a0.w;
            af[4]=a1.x; af[5]=a1.y; af[6]=a1.z; af[7]=a1.w;
            float4 b0 = *(const float4*)&Bs[k][tx * 4];
            bf[0]=b0.x; bf[1]=b0.y; bf[2]=b0.z; bf[3]=b0.w;
            #pragma unroll
            for (int i = 0; i < 8; i++)
                #pragma unroll
                for (int j = 0; j < 4; j++)
                    acc[i][j] += af[i] * bf[j];
        }
        __syncthreads();
    }
    #pragma unroll
    for (int i = 0; i < 8; i++) {
        int row = bm + ty * 8 + i;
        if (row < M) {
            #pragma unroll
            for (int j = 0; j < 4; j++) {
                int col = bn + tx * 4 + j;
                C[(size_t)row * EE + col] = acc[i][j] + bias[col];
            }
        }
    }
}

// ---------------------------------------------------------------------------
// Attention: block = (b*H+h, s-split). 128 threads; thread t owns query row t
// (t < 100). Online softmax over its S-chunk; K/V tiles staged in smem
// (compute reads are warp-uniform -> broadcast). Mask is int32 (0/1).
// ---------------------------------------------------------------------------
#define SC 64
#define SCHUNK (SS / SPLIT)   // 1024
__global__ __launch_bounds__(128)
void attn_kernel(const int* __restrict__ mask) {
    int bh = blockIdx.x;      // 0..127
    int sp = blockIdx.y;      // 0..SPLIT-1
    int b = bh >> 3, h = bh & 7;
    int t = threadIdx.x;

    __shared__ float ks[SC][36];
    __shared__ float vs[SC][36];

    const float scale = 0.17677669529663687f;  // 1/sqrt(32)
    float qv[HD];
    if (t < QQ) {
        const float* qp = g_Qp + ((size_t)(b * QQ + t)) * EE + h * HD;
        #pragma unroll
        for (int d = 0; d < HD; d++) qv[d] = qp[d] * scale;
    }
    float m = -INFINITY, l = 0.f;
    float acc[HD];
    #pragma unroll
    for (int d = 0; d < HD; d++) acc[d] = 0.f;

    const float* Kb = g_K + ((size_t)b * SS) * EE + h * HD;
    const float* Vb = g_V + ((size_t)b * SS) * EE + h * HD;
    const int* mrow = mask + ((size_t)(b * QQ + (t < QQ ? t : 0))) * SS;

    int s_begin = sp * SCHUNK;
    for (int c0 = 0; c0 < SCHUNK; c0 += SC) {
        int sbase = s_begin + c0;
        // cooperative tile load: 8 threads per row (float4 over HD=32)
        {
            int g  = t >> 3;          // 0..15
            int d4 = (t & 7) * 4;
            #pragma unroll
            for (int ss0 = 0; ss0 < SC; ss0 += 16) {
                int s = g + ss0;
                float4 kv4 = *(const float4*)(Kb + (size_t)(sbase + s) * EE + d4);
                float4 vv4 = *(const float4*)(Vb + (size_t)(sbase + s) * EE + d4);
                ks[s][d4+0]=kv4.x; ks[s][d4+1]=kv4.y; ks[s][d4+2]=kv4.z; ks[s][d4+3]=kv4.w;
                vs[s][d4+0]=vv4.x; vs[s][d4+1]=vv4.y; vs[s][d4+2]=vv4.z; vs[s][d4+3]=vv4.w;
            }
        }
        __syncthreads();
        if (t < QQ) {
            #pragma unroll
            for (int s4 = 0; s4 < SC / 4; s4++) {
                int4 mm = *(const int4*)(mrow + sbase + s4 * 4);
                int mk[4] = {mm.x, mm.y, mm.z, mm.w};
                #pragma unroll
                for (int j = 0; j < 4; j++) {
                    int s = s4 * 4 + j;
                    float p0 = 0.f, p1 = 0.f, p2 = 0.f, p3 = 0.f;
                    #pragma unroll
                    for (int d = 0; d < HD; d += 4) {
                        p0 += qv[d + 0] * ks[s][d + 0];
                        p1 += qv[d + 1] * ks[s][d + 1];
                        p2 += qv[d + 2] * ks[s][d + 2];
                        p3 += qv[d + 3] * ks[s][d + 3];
                    }
                    float sc = (p0 + p1) + (p2 + p3);
                    if (mk[j] == 0) sc = NEGBIG;
                    if (sc > m) {
                        float corr = __expf(m - sc);
                        l = l * corr + 1.f;
                        #pragma unroll
                        for (int d = 0; d < HD; d++)
                            acc[d] = acc[d] * corr + vs[s][d];
                        m = sc;
                    } else {
                        float p = __expf(sc - m);
                        l += p;
                        #pragma unroll
                        for (int d = 0; d < HD; d++)
                            acc[d] += p * vs[s][d];
                    }
                }
            }
        }
        __syncthreads();
    }
    if (t < QQ) {
        size_t idx = ((size_t)(bh * SPLIT + sp)) * QQ + t;
        g_Pm[idx] = m;
        g_Pl[idx] = l;
        float* pa = g_Pacc + idx * HD;
        #pragma unroll
        for (int d = 0; d < HD; d++) pa[d] = acc[d];
    }
}

// ---------------------------------------------------------------------------
// Merge SPLIT partials; one warp per (b,h,q), lane = head dim.
// ---------------------------------------------------------------------------
__global__ __launch_bounds__(256)
void attn_merge() {
    int warp = (blockIdx.x * blockDim.x + threadIdx.x) >> 5;
    int lane = threadIdx.x & 31;
    if (warp >= BB * HH * QQ) return;
    int bh = warp / QQ, q = warp % QQ;
    int b = bh >> 3, h = bh & 7;
    float M = -INFINITY;
    #pragma unroll
    for (int i = 0; i < SPLIT; i++)
        M = fmaxf(M, g_Pm[(size_t)(bh * SPLIT + i) * QQ + q]);
    float L = 0.f, o = 0.f;
    #pragma unroll
    for (int i = 0; i < SPLIT; i++) {
        size_t idx = (size_t)(bh * SPLIT + i) * QQ + q;
        float w = __expf(g_Pm[idx] - M);
        L += g_Pl[idx] * w;
        o += g_Pacc[idx * HD + lane] * w;
    }
    g_attn[((size_t)(b * QQ + q)) * EE + h * HD + lane] = o / L;
}

// ---------------------------------------------------------------------------
extern "C" void kernel_launch(void* const* d_in, const int* in_sizes, int n_in,
                              void* d_out, int out_size) {
    const float* query_features = (const float*)d_in[0];
    const float* image_features = (const float*)d_in[1];
    const int*   mask           = (const int*)d_in[2];
    const float* pos_query      = (const float*)d_in[3];
    const float* pos_image      = (const float*)d_in[4];
    const float* Wq = (const float*)d_in[5];
    const float* bq = (const float*)d_in[6];
    const float* Wk = (const float*)d_in[7];
    const float* bk = (const float*)d_in[8];
    const float* Wv = (const float*)d_in[9];
    const float* bv = (const float*)d_in[10];
    const float* Wo = (const float*)d_in[11];
    const float* bo = (const float*)d_in[12];
    float* out = (float*)d_out;

    float* imgT; cudaGetSymbolAddress((void**)&imgT, g_imgT);
    float* Kp;   cudaGetSymbolAddress((void**)&Kp,   g_K);
    float* Vp;   cudaGetSymbolAddress((void**)&Vp,   g_V);
    float* Qp;   cudaGetSymbolAddress((void**)&Qp,   g_Qp);
    float* attn; cudaGetSymbolAddress((void**)&attn, g_attn);

    // 1. transpose image features -> (B*S, E)
    {
        dim3 grid(SS / 32, EE / 32, BB);
        dim3 blk(32, 8);
        transpose_img<<<grid, blk>>>(image_features);
    }
    // 2. Q projection: (B*Q, E)
    {
        int M = BB * QQ;
        dim3 grid((M + GBM - 1) / GBM, EE / GBN);
        sgemm_nt<<<grid, 256>>>(query_features, pos_query, Wq, bq, Qp, M);
    }
    // 3. K projection: (B*S, E)
    {
        int M = BB * SS;
        dim3 grid(M / GBM, EE / GBN);
        sgemm_nt<<<grid, 256>>>(imgT, pos_image, Wk, bk, Kp, M);
    }
    // 4. V projection
    {
        int M = BB * SS;
        dim3 grid(M / GBM, EE / GBN);
        sgemm_nt<<<grid, 256>>>(imgT, nullptr, Wv, bv, Vp, M);
    }
    // 5. attention partials
    {
        dim3 grid(BB * HH, SPLIT);
        attn_kernel<<<grid, 128>>>(mask);
    }
    // 6. merge partials
    {
        int nthreads = BB * HH * QQ * 32;
        attn_merge<<<(nthreads + 255) / 256, 256>>>();
    }
    // 7. output projection
    {
        int M = BB * QQ;
        dim3 grid((M + GBM - 1) / GBM, EE / GBN);
        sgemm_nt<<<grid, 256>>>(attn, nullptr, Wo, bo, out, M);
    }
}

// round 3
// speedup vs baseline: 1.3687x; 1.3687x over previous
#include <cuda_runtime.h>
#include <cuda_bf16.h>
#include <math.h>

// Problem constants
#define BB 16
#define QQ 100
#define EE 256
#define HH 8
#define HD 32
#define SS 4096
#define NEGBIG (-1e9f)

// Scratch (device globals: allocation-free rule)
__device__ float g_imgT[(size_t)BB * SS * EE];   // (B*S, E) row-major
__device__ float g_K[(size_t)BB * SS * EE];
__device__ float g_V[(size_t)BB * SS * EE];
__device__ float g_Qp[(size_t)BB * QQ * EE];
__device__ float g_attn[(size_t)BB * QQ * EE];

#define SPLIT 8
#define NPART (BB * HH * SPLIT * QQ)
__device__ float g_Pm[NPART];
__device__ float g_Pl[NPART];
__device__ float g_Pacc[(size_t)NPART * HD];

// ---------------------------------------------------------------------------
// Transpose image_features (B, E, S) -> g_imgT (B*S, E)
// ---------------------------------------------------------------------------
__global__ void transpose_img(const float* __restrict__ img) {
    __shared__ float tile[32][33];
    int b = blockIdx.z;
    int e0 = blockIdx.y * 32;
    int s0 = blockIdx.x * 32;
    int tx = threadIdx.x, ty = threadIdx.y;  // 32 x 8
    const float* ip = img + ((size_t)b * EE + e0) * SS + s0;
    #pragma unroll
    for (int i = ty; i < 32; i += 8)
        tile[i][tx] = ip[(size_t)i * SS + tx];          // tile[e][s]
    __syncthreads();
    float* op = g_imgT + ((size_t)b * SS + s0) * EE + e0;
    #pragma unroll
    for (int i = ty; i < 32; i += 8)
        op[(size_t)i * EE + tx] = tile[tx][i];          // out[s][e]
}

// ---------------------------------------------------------------------------
// C[r,n] = sum_c (A1[r,c] (+A2[r,c])) * W[n,c] + bias[n]
// K == N == 256. BM=BN=128, BK=8, 256 threads, 8x8 microtile, double-buffered.
// ---------------------------------------------------------------------------
#define TBM 128
#define TBN 128
#define TBK 8
__global__ __launch_bounds__(256)
void sgemm_nt(const float* __restrict__ A1, const float* __restrict__ A2,
              const float* __restrict__ W, const float* __restrict__ bias,
              float* __restrict__ C, int M) {
    __shared__ float As[2][TBK][TBM + 4];
    __shared__ float Bs[2][TBK][TBN + 4];
    int bm = blockIdx.x * TBM;
    int bn = blockIdx.y * TBN;
    int tid = threadIdx.x;
    int tx = tid & 15, ty = tid >> 4;
    int lr = tid >> 1;          // 0..127: row within tile (for loads)
    int lc = (tid & 1) * 4;     // 0 or 4: k-offset within BK=8

    float acc[8][8];
    #pragma unroll
    for (int i = 0; i < 8; i++)
        #pragma unroll
        for (int j = 0; j < 8; j++) acc[i][j] = 0.f;

    // prologue: load k0=0 tile into buffer 0
    {
        int row = bm + lr;
        float4 av = make_float4(0.f, 0.f, 0.f, 0.f);
        if (row < M) {
            av = *(const float4*)(A1 + (size_t)row * EE + lc);
            if (A2) {
                float4 p = *(const float4*)(A2 + (size_t)row * EE + lc);
                av.x += p.x; av.y += p.y; av.z += p.z; av.w += p.w;
            }
        }
        As[0][lc + 0][lr] = av.x;
        As[0][lc + 1][lr] = av.y;
        As[0][lc + 2][lr] = av.z;
        As[0][lc + 3][lr] = av.w;
        float4 wv = *(const float4*)(W + (size_t)(bn + lr) * EE + lc);
        Bs[0][lc + 0][lr] = wv.x;
        Bs[0][lc + 1][lr] = wv.y;
        Bs[0][lc + 2][lr] = wv.z;
        Bs[0][lc + 3][lr] = wv.w;
    }
    __syncthreads();

    int buf = 0;
    for (int k0 = 0; k0 < EE; k0 += TBK) {
        bool nxt = (k0 + TBK) < EE;
        float4 av, wv;
        if (nxt) {
            int row = bm + lr;
            av = make_float4(0.f, 0.f, 0.f, 0.f);
            if (row < M) {
                av = *(const float4*)(A1 + (size_t)row * EE + k0 + TBK + lc);
                if (A2) {
                    float4 p = *(const float4*)(A2 + (size_t)row * EE + k0 + TBK + lc);
                    av.x += p.x; av.y += p.y; av.z += p.z; av.w += p.w;
                }
            }
            wv = *(const float4*)(W + (size_t)(bn + lr) * EE + k0 + TBK + lc);
        }
        #pragma unroll
        for (int k = 0; k < TBK; k++) {
            float af[8], bf[8];
            *(float4*)(af)     = *(const float4*)&As[buf][k][ty * 8];
            *(float4*)(af + 4) = *(const float4*)&As[buf][k][ty * 8 + 4];
            *(float4*)(bf)     = *(const float4*)&Bs[buf][k][tx * 8];
            *(float4*)(bf + 4) = *(const float4*)&Bs[buf][k][tx * 8 + 4];
            #pragma unroll
            for (int i = 0; i < 8; i++)
                #pragma unroll
                for (int j = 0; j < 8; j++)
                    acc[i][j] += af[i] * bf[j];
        }
        if (nxt) {
            int nb = buf ^ 1;
            As[nb][lc + 0][lr] = av.x;
            As[nb][lc + 1][lr] = av.y;
            As[nb][lc + 2][lr] = av.z;
            As[nb][lc + 3][lr] = av.w;
            Bs[nb][lc + 0][lr] = wv.x;
            Bs[nb][lc + 1][lr] = wv.y;
            Bs[nb][lc + 2][lr] = wv.z;
            Bs[nb][lc + 3][lr] = wv.w;
            __syncthreads();
            buf = nb;
        }
    }

    #pragma unroll
    for (int i = 0; i < 8; i++) {
        int row = bm + ty * 8 + i;
        if (row < M) {
            #pragma unroll
            for (int j = 0; j < 8; j++) {
                int col = bn + tx * 8 + j;
                C[(size_t)row * EE + col] = acc[i][j] + bias[col];
            }
        }
    }
}

// ---------------------------------------------------------------------------
// Attention: block = (b*H+h, s-split). 128 threads; thread t owns query row t.
// Branch-free online softmax with per-16 chunk rescale. Mask int32.
// ---------------------------------------------------------------------------
#define SC 64
#define CH 16
#define SCHUNK (SS / SPLIT)   // 512
__global__ __launch_bounds__(128)
void attn_kernel(const int* __restrict__ mask) {
    int bh = blockIdx.x;      // 0..127
    int sp = blockIdx.y;      // 0..SPLIT-1
    int b = bh >> 3, h = bh & 7;
    int t = threadIdx.x;

    __shared__ float ks[SC][36];
    __shared__ float vs[SC][36];

    const float scale = 0.17677669529663687f;  // 1/sqrt(32)
    float qv[HD];
    if (t < QQ) {
        const float* qp = g_Qp + ((size_t)(b * QQ + t)) * EE + h * HD;
        #pragma unroll
        for (int d = 0; d < HD; d++) qv[d] = qp[d] * scale;
    }
    float m = -INFINITY, l = 0.f;
    float acc[HD];
    #pragma unroll
    for (int d = 0; d < HD; d++) acc[d] = 0.f;

    const float* Kb = g_K + ((size_t)b * SS) * EE + h * HD;
    const float* Vb = g_V + ((size_t)b * SS) * EE + h * HD;
    const int* mrow = mask + ((size_t)(b * QQ + (t < QQ ? t : 0))) * SS;

    int s_begin = sp * SCHUNK;
    for (int c0 = 0; c0 < SCHUNK; c0 += SC) {
        int sbase = s_begin + c0;
        // cooperative tile load: 8 threads per row (float4 over HD=32)
        {
            int g  = t >> 3;          // 0..15
            int d4 = (t & 7) * 4;
            #pragma unroll
            for (int ss0 = 0; ss0 < SC; ss0 += 16) {
                int s = g + ss0;
                float4 kv4 = *(const float4*)(Kb + (size_t)(sbase + s) * EE + d4);
                float4 vv4 = *(const float4*)(Vb + (size_t)(sbase + s) * EE + d4);
                ks[s][d4+0]=kv4.x; ks[s][d4+1]=kv4.y; ks[s][d4+2]=kv4.z; ks[s][d4+3]=kv4.w;
                vs[s][d4+0]=vv4.x; vs[s][d4+1]=vv4.y; vs[s][d4+2]=vv4.z; vs[s][d4+3]=vv4.w;
            }
        }
        __syncthreads();
        if (t < QQ) {
            #pragma unroll
            for (int c16 = 0; c16 < SC; c16 += CH) {
                int mi[CH];
                #pragma unroll
                for (int j4 = 0; j4 < CH; j4 += 4) {
                    int4 mm = *(const int4*)(mrow + sbase + c16 + j4);
                    mi[j4 + 0] = mm.x; mi[j4 + 1] = mm.y;
                    mi[j4 + 2] = mm.z; mi[j4 + 3] = mm.w;
                }
                float sc[CH];
                #pragma unroll
                for (int j = 0; j < CH; j++) {
                    int s = c16 + j;
                    float p0 = 0.f, p1 = 0.f, p2 = 0.f, p3 = 0.f;
                    #pragma unroll
                    for (int d = 0; d < HD; d += 4) {
                        p0 += qv[d + 0] * ks[s][d + 0];
                        p1 += qv[d + 1] * ks[s][d + 1];
                        p2 += qv[d + 2] * ks[s][d + 2];
                        p3 += qv[d + 3] * ks[s][d + 3];
                    }
                    float v = (p0 + p1) + (p2 + p3);
                    sc[j] = (mi[j] != 0) ? v : NEGBIG;
                }
                float tmax = sc[0];
                #pragma unroll
                for (int j = 1; j < CH; j++) tmax = fmaxf(tmax, sc[j]);
                float mnew = fmaxf(m, tmax);
                float corr = __expf(m - mnew);
                m = mnew;
                l *= corr;
                #pragma unroll
                for (int d = 0; d < HD; d++) acc[d] *= corr;
                #pragma unroll
                for (int j = 0; j < CH; j++) {
                    int s = c16 + j;
                    float p = __expf(sc[j] - m);
                    l += p;
                    #pragma unroll
                    for (int d = 0; d < HD; d++)
                        acc[d] += p * vs[s][d];
                }
            }
        }
        __syncthreads();
    }
    if (t < QQ) {
        size_t idx = ((size_t)(bh * SPLIT + sp)) * QQ + t;
        g_Pm[idx] = m;
        g_Pl[idx] = l;
        float* pa = g_Pacc + idx * HD;
        #pragma unroll
        for (int d = 0; d < HD; d++) pa[d] = acc[d];
    }
}

// ---------------------------------------------------------------------------
// Merge SPLIT partials; one warp per (b,h,q), lane = head dim.
// ---------------------------------------------------------------------------
__global__ __launch_bounds__(256)
void attn_merge() {
    int warp = (blockIdx.x * blockDim.x + threadIdx.x) >> 5;
    int lane = threadIdx.x & 31;
    if (warp >= BB * HH * QQ) return;
    int bh = warp / QQ, q = warp % QQ;
    int b = bh >> 3, h = bh & 7;
    float M = -INFINITY;
    #pragma unroll
    for (int i = 0; i < SPLIT; i++)
        M = fmaxf(M, g_Pm[(size_t)(bh * SPLIT + i) * QQ + q]);
    float L = 0.f, o = 0.f;
    #pragma unroll
    for (int i = 0; i < SPLIT; i++) {
        size_t idx = (size_t)(bh * SPLIT + i) * QQ + q;
        float w = __expf(g_Pm[idx] - M);
        L += g_Pl[idx] * w;
        o += g_Pacc[idx * HD + lane] * w;
    }
    g_attn[((size_t)(b * QQ + q)) * EE + h * HD + lane] = o / L;
}

// ---------------------------------------------------------------------------
extern "C" void kernel_launch(void* const* d_in, const int* in_sizes, int n_in,
                              void* d_out, int out_size) {
    const float* query_features = (const float*)d_in[0];
    const float* image_features = (const float*)d_in[1];
    const int*   mask           = (const int*)d_in[2];
    const float* pos_query      = (const float*)d_in[3];
    const float* pos_image      = (const float*)d_in[4];
    const float* Wq = (const float*)d_in[5];
    const float* bq = (const float*)d_in[6];
    const float* Wk = (const float*)d_in[7];
    const float* bk = (const float*)d_in[8];
    const float* Wv = (const float*)d_in[9];
    const float* bv = (const float*)d_in[10];
    const float* Wo = (const float*)d_in[11];
    const float* bo = (const float*)d_in[12];
    float* out = (float*)d_out;

    float* imgT; cudaGetSymbolAddress((void**)&imgT, g_imgT);
    float* Kp;   cudaGetSymbolAddress((void**)&Kp,   g_K);
    float* Vp;   cudaGetSymbolAddress((void**)&Vp,   g_V);
    float* Qp;   cudaGetSymbolAddress((void**)&Qp,   g_Qp);
    float* attn; cudaGetSymbolAddress((void**)&attn, g_attn);

    // 1. transpose image features -> (B*S, E)
    {
        dim3 grid(SS / 32, EE / 32, BB);
        dim3 blk(32, 8);
        transpose_img<<<grid, blk>>>(image_features);
    }
    // 2. Q projection: (B*Q, E)
    {
        int M = BB * QQ;
        dim3 grid((M + TBM - 1) / TBM, EE / TBN);
        sgemm_nt<<<grid, 256>>>(query_features, pos_query, Wq, bq, Qp, M);
    }
    // 3. K projection: (B*S, E)
    {
        int M = BB * SS;
        dim3 grid(M / TBM, EE / TBN);
        sgemm_nt<<<grid, 256>>>(imgT, pos_image, Wk, bk, Kp, M);
    }
    // 4. V projection
    {
        int M = BB * SS;
        dim3 grid(M / TBM, EE / TBN);
        sgemm_nt<<<grid, 256>>>(imgT, nullptr, Wv, bv, Vp, M);
    }
    // 5. attention partials
    {
        dim3 grid(BB * HH, SPLIT);
        attn_kernel<<<grid, 128>>>(mask);
    }
    // 6. merge partials
    {
        int nthreads = BB * HH * QQ * 32;
        attn_merge<<<(nthreads + 255) / 256, 256>>>();
    }
    // 7. output projection
    {
        int M = BB * QQ;
        dim3 grid((M + TBM - 1) / TBM, EE / TBN);
        sgemm_nt<<<grid, 256>>>(attn, nullptr, Wo, bo, out, M);
    }
}

// round 5
// speedup vs baseline: 2.1817x; 1.5940x over previous
#include <cuda_runtime.h>
#include <cuda_bf16.h>
#include <cstdint>
#include <math.h>

// Problem constants
#define BB 16
#define QQ 100
#define EE 256
#define HH 8
#define HD 32
#define SS 4096
#define NEGBIG (-1e9f)

// Scratch (device globals: allocation-free rule)
__device__ float g_imgT[(size_t)BB * SS * EE];   // (B*S, E) row-major
__device__ float g_K[(size_t)BB * SS * EE];
__device__ float g_V[(size_t)BB * SS * EE];
__device__ float g_Qp[(size_t)BB * QQ * EE];
__device__ float g_attn[(size_t)BB * QQ * EE];

#define SPLIT 8
#define NPART (BB * HH * SPLIT * QQ)
__device__ float g_Pm[NPART];
__device__ float g_Pl[NPART];
__device__ float g_Pacc[(size_t)NPART * HD];

__device__ __forceinline__ uint32_t f2tf32(float f) {
    uint32_t u;
    asm("cvt.rna.tf32.f32 %0, %1;" : "=r"(u) : "f"(f));
    return u;
}
__device__ __forceinline__ void mma_tf32(float c[4], const uint32_t a[4],
                                         const uint32_t b[2]) {
    asm volatile(
        "mma.sync.aligned.m16n8k8.row.col.f32.tf32.tf32.f32 "
        "{%0,%1,%2,%3}, {%4,%5,%6,%7}, {%8,%9}, {%0,%1,%2,%3};"
        : "+f"(c[0]), "+f"(c[1]), "+f"(c[2]), "+f"(c[3])
        : "r"(a[0]), "r"(a[1]), "r"(a[2]), "r"(a[3]), "r"(b[0]), "r"(b[1]));
}

// ===========================================================================
// Transpose image_features (B, E, S) -> g_imgT (B*S, E)
// ===========================================================================
__global__ void transpose_img(const float* __restrict__ img) {
    __shared__ float tile[32][33];
    int b = blockIdx.z;
    int e0 = blockIdx.y * 32;
    int s0 = blockIdx.x * 32;
    int tx = threadIdx.x, ty = threadIdx.y;  // 32 x 8
    const float* ip = img + ((size_t)b * EE + e0) * SS + s0;
    #pragma unroll
    for (int i = ty; i < 32; i += 8)
        tile[i][tx] = ip[(size_t)i * SS + tx];
    __syncthreads();
    float* op = g_imgT + ((size_t)b * SS + s0) * EE + e0;
    #pragma unroll
    for (int i = ty; i < 32; i += 8)
        op[(size_t)i * EE + tx] = tile[tx][i];
}

// ===========================================================================
// tf32 mma.sync GEMM: C[r,n] = sum_c (A1[r,c](+A2[r,c])) * W[n,c] + bias[n]
// N = K = 256 fixed. Tile 128x128, BK=16, 256 threads (8 warps, 32x64 each).
// ===========================================================================
#define MBK 16
#define SPITCH 20   // smem row pitch in words (16B-aligned float4 stores)
__global__ __launch_bounds__(256)
void mma_gemm(const float* __restrict__ A1, const float* __restrict__ A2,
              const float* __restrict__ W, const float* __restrict__ bias,
              float* __restrict__ C, int M) {
    __shared__ uint32_t As[2][128 * SPITCH];
    __shared__ uint32_t Bs[2][128 * SPITCH];

    int tid = threadIdx.x;
    int wid = tid >> 5, lane = tid & 31;
    int bm = blockIdx.x * 128;
    int bn = blockIdx.y * 128;
    int wm = (wid & 3) * 32;
    int wn = (wid >> 2) * 64;
    int lrow = tid >> 1;          // 0..127
    int lkb  = (tid & 1) * 8;     // 0 or 8

    int lg = lane >> 2;           // 0..7
    int lk = lane & 3;            // 0..3

    float c[2][8][4];
    #pragma unroll
    for (int mf = 0; mf < 2; mf++)
        #pragma unroll
        for (int nf = 0; nf < 8; nf++)
            #pragma unroll
            for (int i = 0; i < 4; i++) c[mf][nf][i] = 0.f;

    // ---- global fetch of k-tile kt into registers ----
    float a0x, a0y, a0z, a0w, a1x, a1y, a1z, a1w;
    float w0x, w0y, w0z, w0w, w1x, w1y, w1z, w1w;
    auto fetch = [&](int kt) {
        float4 a0 = make_float4(0.f, 0.f, 0.f, 0.f), a1 = a0;
        int row = bm + lrow;
        if (row < M) {
            const float* ap = A1 + (size_t)row * EE + kt * MBK + lkb;
            a0 = ((const float4*)ap)[0];
            a1 = ((const float4*)ap)[1];
            if (A2) {
                const float* pp = A2 + (size_t)row * EE + kt * MBK + lkb;
                float4 p0 = ((const float4*)pp)[0];
                float4 p1 = ((const float4*)pp)[1];
                a0.x += p0.x; a0.y += p0.y; a0.z += p0.z; a0.w += p0.w;
                a1.x += p1.x; a1.y += p1.y; a1.z += p1.z; a1.w += p1.w;
            }
        }
        const float* wp = W + (size_t)(bn + lrow) * EE + kt * MBK + lkb;
        float4 b0 = ((const float4*)wp)[0];
        float4 b1 = ((const float4*)wp)[1];
        a0x = a0.x; a0y = a0.y; a0z = a0.z; a0w = a0.w;
        a1x = a1.x; a1y = a1.y; a1z = a1.z; a1w = a1.w;
        w0x = b0.x; w0y = b0.y; w0z = b0.z; w0w = b0.w;
        w1x = b1.x; w1y = b1.y; w1z = b1.z; w1w = b1.w;
    };
    auto stage = [&](int buf) {
        uint32_t* ad = &As[buf][lrow * SPITCH + lkb];
        ad[0] = f2tf32(a0x); ad[1] = f2tf32(a0y);
        ad[2] = f2tf32(a0z); ad[3] = f2tf32(a0w);
        ad[4] = f2tf32(a1x); ad[5] = f2tf32(a1y);
        ad[6] = f2tf32(a1z); ad[7] = f2tf32(a1w);
        uint32_t* bd = &Bs[buf][lrow * SPITCH + lkb];
        bd[0] = f2tf32(w0x); bd[1] = f2tf32(w0y);
        bd[2] = f2tf32(w0z); bd[3] = f2tf32(w0w);
        bd[4] = f2tf32(w1x); bd[5] = f2tf32(w1y);
        bd[6] = f2tf32(w1z); bd[7] = f2tf32(w1w);
    };

    fetch(0);
    stage(0);
    __syncthreads();

    #pragma unroll 1
    for (int kt = 0; kt < 16; kt++) {
        int buf = kt & 1;
        if (kt < 15) fetch(kt + 1);
        #pragma unroll
        for (int ks8 = 0; ks8 < 2; ks8++) {
            int kk = ks8 * 8;
            uint32_t af[2][4];
            #pragma unroll
            for (int mf = 0; mf < 2; mf++) {
                int r = wm + mf * 16 + lg;
                const uint32_t* base = &As[buf][0];
                af[mf][0] = base[r * SPITCH + kk + lk];
                af[mf][1] = base[(r + 8) * SPITCH + kk + lk];
                af[mf][2] = base[r * SPITCH + kk + lk + 4];
                af[mf][3] = base[(r + 8) * SPITCH + kk + lk + 4];
            }
            uint32_t bf[8][2];
            #pragma unroll
            for (int nf = 0; nf < 8; nf++) {
                int n = wn + nf * 8 + lg;
                bf[nf][0] = Bs[buf][n * SPITCH + kk + lk];
                bf[nf][1] = Bs[buf][n * SPITCH + kk + lk + 4];
            }
            #pragma unroll
            for (int mf = 0; mf < 2; mf++)
                #pragma unroll
                for (int nf = 0; nf < 8; nf++)
                    mma_tf32(c[mf][nf], af[mf], bf[nf]);
        }
        if (kt < 15) {
            stage(buf ^ 1);
            __syncthreads();
        }
    }

    // epilogue: float2 stores + bias
    #pragma unroll
    for (int mf = 0; mf < 2; mf++) {
        int r0 = bm + wm + mf * 16 + lg;
        #pragma unroll
        for (int nf = 0; nf < 8; nf++) {
            int cc = bn + wn + nf * 8 + lk * 2;
            float bx = bias[cc], by = bias[cc + 1];
            if (r0 < M) {
                float2 o = make_float2(c[mf][nf][0] + bx, c[mf][nf][1] + by);
                *(float2*)(C + (size_t)r0 * EE + cc) = o;
            }
            if (r0 + 8 < M) {
                float2 o = make_float2(c[mf][nf][2] + bx, c[mf][nf][3] + by);
                *(float2*)(C + (size_t)(r0 + 8) * EE + cc) = o;
            }
        }
    }
}

// ===========================================================================
// Attention: branch-free online softmax, float4 LDS. Mask int32.
// ===========================================================================
#define SC 64
#define CH 16
#define SCHUNK (SS / SPLIT)   // 512
__global__ __launch_bounds__(128)
void attn_kernel(const int* __restrict__ mask) {
    int bh = blockIdx.x;
    int sp = blockIdx.y;
    int b = bh >> 3, h = bh & 7;
    int t = threadIdx.x;

    __shared__ __align__(16) float ks[SC][36];
    __shared__ __align__(16) float vs[SC][36];

    const float scale = 0.17677669529663687f;  // 1/sqrt(32)
    float qv[HD];
    if (t < QQ) {
        const float* qp = g_Qp + ((size_t)(b * QQ + t)) * EE + h * HD;
        #pragma unroll
        for (int d = 0; d < HD; d++) qv[d] = qp[d] * scale;
    }
    float m = -INFINITY, l = 0.f;
    float acc[HD];
    #pragma unroll
    for (int d = 0; d < HD; d++) acc[d] = 0.f;

    const float* Kb = g_K + ((size_t)b * SS) * EE + h * HD;
    const float* Vb = g_V + ((size_t)b * SS) * EE + h * HD;
    const int* mrow = mask + ((size_t)(b * QQ + (t < QQ ? t : 0))) * SS;

    int s_begin = sp * SCHUNK;
    for (int c0 = 0; c0 < SCHUNK; c0 += SC) {
        int sbase = s_begin + c0;
        {
            int g  = t >> 3;
            int d4 = (t & 7) * 4;
            #pragma unroll
            for (int ss0 = 0; ss0 < SC; ss0 += 16) {
                int s = g + ss0;
                float4 kv4 = *(const float4*)(Kb + (size_t)(sbase + s) * EE + d4);
                float4 vv4 = *(const float4*)(Vb + (size_t)(sbase + s) * EE + d4);
                *(float4*)&ks[s][d4] = kv4;
                *(float4*)&vs[s][d4] = vv4;
            }
        }
        __syncthreads();
        if (t < QQ) {
            #pragma unroll
            for (int c16 = 0; c16 < SC; c16 += CH) {
                int mi[CH];
                #pragma unroll
                for (int j4 = 0; j4 < CH; j4 += 4) {
                    int4 mm = *(const int4*)(mrow + sbase + c16 + j4);
                    mi[j4 + 0] = mm.x; mi[j4 + 1] = mm.y;
                    mi[j4 + 2] = mm.z; mi[j4 + 3] = mm.w;
                }
                float sc[CH];
                #pragma unroll
                for (int j = 0; j < CH; j++) {
                    int s = c16 + j;
                    const float4* kp = (const float4*)&ks[s][0];
                    float d0 = 0.f, d1 = 0.f, d2 = 0.f, d3 = 0.f;
                    #pragma unroll
                    for (int dd = 0; dd < 8; dd++) {
                        float4 kv = kp[dd];
                        d0 = fmaf(qv[dd * 4 + 0], kv.x, d0);
                        d1 = fmaf(qv[dd * 4 + 1], kv.y, d1);
                        d2 = fmaf(qv[dd * 4 + 2], kv.z, d2);
                        d3 = fmaf(qv[dd * 4 + 3], kv.w, d3);
                    }
                    float v = (d0 + d1) + (d2 + d3);
                    sc[j] = (mi[j] != 0) ? v : NEGBIG;
                }
                float tmax = sc[0];
                #pragma unroll
                for (int j = 1; j < CH; j++) tmax = fmaxf(tmax, sc[j]);
                float mnew = fmaxf(m, tmax);
                float corr = __expf(m - mnew);
                m = mnew;
                l *= corr;
                #pragma unroll
                for (int d = 0; d < HD; d++) acc[d] *= corr;
                #pragma unroll
                for (int j = 0; j < CH; j++) {
                    int s = c16 + j;
                    float p = __expf(sc[j] - m);
                    l += p;
                    const float4* vp = (const float4*)&vs[s][0];
                    #pragma unroll
                    for (int dd = 0; dd < 8; dd++) {
                        float4 vv = vp[dd];
                        acc[dd * 4 + 0] = fmaf(p, vv.x, acc[dd * 4 + 0]);
                        acc[dd * 4 + 1] = fmaf(p, vv.y, acc[dd * 4 + 1]);
                        acc[dd * 4 + 2] = fmaf(p, vv.z, acc[dd * 4 + 2]);
                        acc[dd * 4 + 3] = fmaf(p, vv.w, acc[dd * 4 + 3]);
                    }
                }
            }
        }
        __syncthreads();
    }
    if (t < QQ) {
        size_t idx = ((size_t)(bh * SPLIT + sp)) * QQ + t;
        g_Pm[idx] = m;
        g_Pl[idx] = l;
        float* pa = g_Pacc + idx * HD;
        #pragma unroll
        for (int d = 0; d < HD; d++) pa[d] = acc[d];
    }
}

// ===========================================================================
// Merge SPLIT partials; one warp per (b,h,q), lane = head dim.
// ===========================================================================
__global__ __launch_bounds__(256)
void attn_merge() {
    int warp = (blockIdx.x * blockDim.x + threadIdx.x) >> 5;
    int lane = threadIdx.x & 31;
    if (warp >= BB * HH * QQ) return;
    int bh = warp / QQ, q = warp % QQ;
    int b = bh >> 3, h = bh & 7;
    float M = -INFINITY;
    #pragma unroll
    for (int i = 0; i < SPLIT; i++)
        M = fmaxf(M, g_Pm[(size_t)(bh * SPLIT + i) * QQ + q]);
    float L = 0.f, o = 0.f;
    #pragma unroll
    for (int i = 0; i < SPLIT; i++) {
        size_t idx = (size_t)(bh * SPLIT + i) * QQ + q;
        float w = __expf(g_Pm[idx] - M);
        L += g_Pl[idx] * w;
        o += g_Pacc[idx * HD + lane] * w;
    }
    g_attn[((size_t)(b * QQ + q)) * EE + h * HD + lane] = o / L;
}

// ===========================================================================
extern "C" void kernel_launch(void* const* d_in, const int* in_sizes, int n_in,
                              void* d_out, int out_size) {
    const float* query_features = (const float*)d_in[0];
    const float* image_features = (const float*)d_in[1];
    const int*   mask           = (const int*)d_in[2];
    const float* pos_query      = (const float*)d_in[3];
    const float* pos_image      = (const float*)d_in[4];
    const float* Wq = (const float*)d_in[5];
    const float* bq = (const float*)d_in[6];
    const float* Wk = (const float*)d_in[7];
    const float* bk = (const float*)d_in[8];
    const float* Wv = (const float*)d_in[9];
    const float* bv = (const float*)d_in[10];
    const float* Wo = (const float*)d_in[11];
    const float* bo = (const float*)d_in[12];
    float* out = (float*)d_out;

    float* imgT; cudaGetSymbolAddress((void**)&imgT, g_imgT);
    float* Kp;   cudaGetSymbolAddress((void**)&Kp,   g_K);
    float* Vp;   cudaGetSymbolAddress((void**)&Vp,   g_V);
    float* Qp;   cudaGetSymbolAddress((void**)&Qp,   g_Qp);
    float* attn; cudaGetSymbolAddress((void**)&attn, g_attn);

    // 1. transpose image features -> (B*S, E)
    {
        dim3 grid(SS / 32, EE / 32, BB);
        dim3 blk(32, 8);
        transpose_img<<<grid, blk>>>(image_features);
    }
    // 2. Q projection
    {
        int M = BB * QQ;
        dim3 grid((M + 127) / 128, 2);
        mma_gemm<<<grid, 256>>>(query_features, pos_query, Wq, bq, Qp, M);
    }
    // 3. K projection
    {
        dim3 grid((BB * SS) / 128, 2);
        mma_gemm<<<grid, 256>>>(imgT, pos_image, Wk, bk, Kp, BB * SS);
    }
    // 4. V projection
    {
        dim3 grid((BB * SS) / 128, 2);
        mma_gemm<<<grid, 256>>>(imgT, nullptr, Wv, bv, Vp, BB * SS);
    }
    // 5. attention partials
    {
        dim3 grid(BB * HH, SPLIT);
        attn_kernel<<<grid, 128>>>(mask);
    }
    // 6. merge partials
    {
        int nthreads = BB * HH * QQ * 32;
        attn_merge<<<(nthreads + 255) / 256, 256>>>();
    }
    // 7. output projection
    {
        int M = BB * QQ;
        dim3 grid((M + 127) / 128, 2);
        mma_gemm<<<grid, 256>>>(attn, nullptr, Wo, bo, out, M);
    }
}

// round 6
// speedup vs baseline: 2.9246x; 1.3405x over previous
#include <cuda_runtime.h>
#include <cuda_bf16.h>
#include <cstdint>
#include <math.h>

// Problem constants
#define BB 16
#define QQ 100
#define EE 256
#define HH 8
#define HD 32
#define SS 4096
#define NEGBIG (-1e9f)

// Scratch (device globals: allocation-free rule)
__device__ float g_imgT[(size_t)BB * SS * EE];   // (B*S, E) row-major
__device__ float g_K[(size_t)BB * SS * EE];
__device__ float g_V[(size_t)BB * SS * EE];
__device__ float g_Qp[(size_t)BB * QQ * EE];
__device__ float g_attn[(size_t)BB * QQ * EE];

#define SPLIT2 4
#define QPAD 128
#define NPART2 (BB * HH * SPLIT2 * QPAD)         // 65536
__device__ float g_Pm[NPART2];
__device__ float g_Pl[NPART2];
__device__ float g_Pacc[(size_t)NPART2 * HD];

__device__ __forceinline__ uint32_t f2tf32(float f) {
    uint32_t u;
    asm("cvt.rna.tf32.f32 %0, %1;" : "=r"(u) : "f"(f));
    return u;
}
__device__ __forceinline__ void split2(float x, float& hi, float& lo) {
    uint32_t u;
    asm("cvt.rna.tf32.f32 %0, %1;" : "=r"(u) : "f"(x));
    hi = __uint_as_float(u);
    float r = x - hi;
    asm("cvt.rna.tf32.f32 %0, %1;" : "=r"(u) : "f"(r));
    lo = __uint_as_float(u);
}
__device__ __forceinline__ void mma_tf32(float c[4], const uint32_t a[4],
                                         const uint32_t b[2]) {
    asm volatile(
        "mma.sync.aligned.m16n8k8.row.col.f32.tf32.tf32.f32 "
        "{%0,%1,%2,%3}, {%4,%5,%6,%7}, {%8,%9}, {%0,%1,%2,%3};"
        : "+f"(c[0]), "+f"(c[1]), "+f"(c[2]), "+f"(c[3])
        : "r"(a[0]), "r"(a[1]), "r"(a[2]), "r"(a[3]), "r"(b[0]), "r"(b[1]));
}
__device__ __forceinline__ void mma_tf32f(float c[4], const float a[4],
                                          const float b0, const float b1) {
    uint32_t A[4] = {__float_as_uint(a[0]), __float_as_uint(a[1]),
                     __float_as_uint(a[2]), __float_as_uint(a[3])};
    uint32_t B[2] = {__float_as_uint(b0), __float_as_uint(b1)};
    mma_tf32(c, A, B);
}

// ===========================================================================
// Transpose image_features (B, E, S) -> g_imgT (B*S, E)
// ===========================================================================
__global__ void transpose_img(const float* __restrict__ img) {
    __shared__ float tile[32][33];
    int b = blockIdx.z;
    int e0 = blockIdx.y * 32;
    int s0 = blockIdx.x * 32;
    int tx = threadIdx.x, ty = threadIdx.y;  // 32 x 8
    const float* ip = img + ((size_t)b * EE + e0) * SS + s0;
    #pragma unroll
    for (int i = ty; i < 32; i += 8)
        tile[i][tx] = ip[(size_t)i * SS + tx];
    __syncthreads();
    float* op = g_imgT + ((size_t)b * SS + s0) * EE + e0;
    #pragma unroll
    for (int i = ty; i < 32; i += 8)
        op[(size_t)i * EE + tx] = tile[tx][i];
}

// ===========================================================================
// tf32 mma.sync GEMM (projections), unchanged from R5.
// ===========================================================================
#define MBK 16
#define SPITCH 20
__global__ __launch_bounds__(256)
void mma_gemm(const float* __restrict__ A1, const float* __restrict__ A2,
              const float* __restrict__ W, const float* __restrict__ bias,
              float* __restrict__ C, int M) {
    __shared__ uint32_t As[2][128 * SPITCH];
    __shared__ uint32_t Bs[2][128 * SPITCH];

    int tid = threadIdx.x;
    int wid = tid >> 5, lane = tid & 31;
    int bm = blockIdx.x * 128;
    int bn = blockIdx.y * 128;
    int wm = (wid & 3) * 32;
    int wn = (wid >> 2) * 64;
    int lrow = tid >> 1;
    int lkb  = (tid & 1) * 8;
    int lg = lane >> 2;
    int lk = lane & 3;

    float c[2][8][4];
    #pragma unroll
    for (int mf = 0; mf < 2; mf++)
        #pragma unroll
        for (int nf = 0; nf < 8; nf++)
            #pragma unroll
            for (int i = 0; i < 4; i++) c[mf][nf][i] = 0.f;

    float a0x, a0y, a0z, a0w, a1x, a1y, a1z, a1w;
    float w0x, w0y, w0z, w0w, w1x, w1y, w1z, w1w;
    auto fetch = [&](int kt) {
        float4 a0 = make_float4(0.f, 0.f, 0.f, 0.f), a1 = a0;
        int row = bm + lrow;
        if (row < M) {
            const float* ap = A1 + (size_t)row * EE + kt * MBK + lkb;
            a0 = ((const float4*)ap)[0];
            a1 = ((const float4*)ap)[1];
            if (A2) {
                const float* pp = A2 + (size_t)row * EE + kt * MBK + lkb;
                float4 p0 = ((const float4*)pp)[0];
                float4 p1 = ((const float4*)pp)[1];
                a0.x += p0.x; a0.y += p0.y; a0.z += p0.z; a0.w += p0.w;
                a1.x += p1.x; a1.y += p1.y; a1.z += p1.z; a1.w += p1.w;
            }
        }
        const float* wp = W + (size_t)(bn + lrow) * EE + kt * MBK + lkb;
        float4 b0 = ((const float4*)wp)[0];
        float4 b1 = ((const float4*)wp)[1];
        a0x = a0.x; a0y = a0.y; a0z = a0.z; a0w = a0.w;
        a1x = a1.x; a1y = a1.y; a1z = a1.z; a1w = a1.w;
        w0x = b0.x; w0y = b0.y; w0z = b0.z; w0w = b0.w;
        w1x = b1.x; w1y = b1.y; w1z = b1.z; w1w = b1.w;
    };
    auto stage = [&](int buf) {
        uint32_t* ad = &As[buf][lrow * SPITCH + lkb];
        ad[0] = f2tf32(a0x); ad[1] = f2tf32(a0y);
        ad[2] = f2tf32(a0z); ad[3] = f2tf32(a0w);
        ad[4] = f2tf32(a1x); ad[5] = f2tf32(a1y);
        ad[6] = f2tf32(a1z); ad[7] = f2tf32(a1w);
        uint32_t* bd = &Bs[buf][lrow * SPITCH + lkb];
        bd[0] = f2tf32(w0x); bd[1] = f2tf32(w0y);
        bd[2] = f2tf32(w0z); bd[3] = f2tf32(w0w);
        bd[4] = f2tf32(w1x); bd[5] = f2tf32(w1y);
        bd[6] = f2tf32(w1z); bd[7] = f2tf32(w1w);
    };

    fetch(0);
    stage(0);
    __syncthreads();

    #pragma unroll 1
    for (int kt = 0; kt < 16; kt++) {
        int buf = kt & 1;
        if (kt < 15) fetch(kt + 1);
        #pragma unroll
        for (int ks8 = 0; ks8 < 2; ks8++) {
            int kk = ks8 * 8;
            uint32_t af[2][4];
            #pragma unroll
            for (int mf = 0; mf < 2; mf++) {
                int r = wm + mf * 16 + lg;
                const uint32_t* base = &As[buf][0];
                af[mf][0] = base[r * SPITCH + kk + lk];
                af[mf][1] = base[(r + 8) * SPITCH + kk + lk];
                af[mf][2] = base[r * SPITCH + kk + lk + 4];
                af[mf][3] = base[(r + 8) * SPITCH + kk + lk + 4];
            }
            uint32_t bf[8][2];
            #pragma unroll
            for (int nf = 0; nf < 8; nf++) {
                int n = wn + nf * 8 + lg;
                bf[nf][0] = Bs[buf][n * SPITCH + kk + lk];
                bf[nf][1] = Bs[buf][n * SPITCH + kk + lk + 4];
            }
            #pragma unroll
            for (int mf = 0; mf < 2; mf++)
                #pragma unroll
                for (int nf = 0; nf < 8; nf++)
                    mma_tf32(c[mf][nf], af[mf], bf[nf]);
        }
        if (kt < 15) {
            stage(buf ^ 1);
            __syncthreads();
        }
    }

    #pragma unroll
    for (int mf = 0; mf < 2; mf++) {
        int r0 = bm + wm + mf * 16 + lg;
        #pragma unroll
        for (int nf = 0; nf < 8; nf++) {
            int cc = bn + wn + nf * 8 + lk * 2;
            float bx = bias[cc], by = bias[cc + 1];
            if (r0 < M) {
                float2 o = make_float2(c[mf][nf][0] + bx, c[mf][nf][1] + by);
                *(float2*)(C + (size_t)r0 * EE + cc) = o;
            }
            if (r0 + 8 < M) {
                float2 o = make_float2(c[mf][nf][2] + bx, c[mf][nf][3] + by);
                *(float2*)(C + (size_t)(r0 + 8) * EE + cc) = o;
            }
        }
    }
}

// ===========================================================================
// Tensor-core flash attention. Block = (b*H+h, s-quarter). 8 warps; warp w
// owns q rows [16w,16w+16). 3-pass tf32 splits for QK and PV (fp32 accuracy).
// ===========================================================================
#define SC2 64
#define NCH (SS / SPLIT2 / SC2)   // 16
__global__ __launch_bounds__(256, 2)
void attn_mma(const int* __restrict__ mask) {
    int bh = blockIdx.x;
    int sp = blockIdx.y;
    int b = bh >> 3, h = bh & 7;
    int tid = threadIdx.x;
    int wid = tid >> 5, lane = tid & 31;
    int lg = lane >> 2, lk = lane & 3;
    int q0 = wid * 16;

    __shared__ __align__(16) float Khi[SC2][36];
    __shared__ __align__(16) float Klo[SC2][36];
    __shared__ __align__(16) float Vhi[SC2][40];
    __shared__ __align__(16) float Vlo[SC2][40];

    const float scale = 0.17677669529663687f;  // 1/sqrt(32)

    // Q fragments (hi/lo), scale folded in
    float aqh[4][4], aql[4][4];
    {
        int r0c = min(q0 + lg, QQ - 1);
        int r1c = min(q0 + lg + 8, QQ - 1);
        const float* Q0 = g_Qp + ((size_t)(b * QQ + r0c)) * EE + h * HD;
        const float* Q1 = g_Qp + ((size_t)(b * QQ + r1c)) * EE + h * HD;
        #pragma unroll
        for (int ks = 0; ks < 4; ks++) {
            split2(Q0[8 * ks + lk] * scale,     aqh[ks][0], aql[ks][0]);
            split2(Q1[8 * ks + lk] * scale,     aqh[ks][1], aql[ks][1]);
            split2(Q0[8 * ks + lk + 4] * scale, aqh[ks][2], aql[ks][2]);
            split2(Q1[8 * ks + lk + 4] * scale, aqh[ks][3], aql[ks][3]);
        }
    }

    float m0 = -INFINITY, m1 = -INFINITY, l0 = 0.f, l1 = 0.f;
    float o[4][4];
    #pragma unroll
    for (int nf = 0; nf < 4; nf++)
        #pragma unroll
        for (int v = 0; v < 4; v++) o[nf][v] = 0.f;

    const float* Kb = g_K + ((size_t)b * SS) * EE + h * HD;
    const float* Vb = g_V + ((size_t)b * SS) * EE + h * HD;
    const int* mrow0 = mask + ((size_t)(b * QQ + min(q0 + lg, QQ - 1))) * SS;
    const int* mrow1 = mask + ((size_t)(b * QQ + min(q0 + lg + 8, QQ - 1))) * SS;

    int s00 = sp * (SS / SPLIT2);

    #pragma unroll 1
    for (int ch = 0; ch < NCH; ch++) {
        int sbase = s00 + ch * SC2;
        // ---- load K/V chunk, split hi/lo into smem ----
        {
            int s = tid >> 2;
            int d0 = (tid & 3) * 8;
            const float* kp = Kb + (size_t)(sbase + s) * EE + d0;
            const float* vp = Vb + (size_t)(sbase + s) * EE + d0;
            float4 k0 = ((const float4*)kp)[0];
            float4 k1 = ((const float4*)kp)[1];
            float4 v0 = ((const float4*)vp)[0];
            float4 v1 = ((const float4*)vp)[1];
            float kk[8] = {k0.x, k0.y, k0.z, k0.w, k1.x, k1.y, k1.z, k1.w};
            float vv[8] = {v0.x, v0.y, v0.z, v0.w, v1.x, v1.y, v1.z, v1.w};
            #pragma unroll
            for (int i = 0; i < 8; i++) {
                float hi, lo;
                split2(kk[i], hi, lo);
                Khi[s][d0 + i] = hi; Klo[s][d0 + i] = lo;
                split2(vv[i], hi, lo);
                Vhi[s][d0 + i] = hi; Vlo[s][d0 + i] = lo;
            }
        }
        __syncthreads();

        // ---- S = Q K^T (3-pass) ----
        float c[8][4];
        #pragma unroll
        for (int nf = 0; nf < 8; nf++)
            #pragma unroll
            for (int v = 0; v < 4; v++) c[nf][v] = 0.f;
        #pragma unroll
        for (int ks = 0; ks < 4; ks++) {
            #pragma unroll
            for (int nf = 0; nf < 8; nf++) {
                int n = 8 * nf + lg;
                float bh0 = Khi[n][8 * ks + lk];
                float bh1 = Khi[n][8 * ks + lk + 4];
                float bl0 = Klo[n][8 * ks + lk];
                float bl1 = Klo[n][8 * ks + lk + 4];
                mma_tf32f(c[nf], aqh[ks], bh0, bh1);
                mma_tf32f(c[nf], aqh[ks], bl0, bl1);
                mma_tf32f(c[nf], aql[ks], bh0, bh1);
            }
        }

        // ---- mask + online softmax on fragments ----
        float mx0 = -INFINITY, mx1 = -INFINITY;
        #pragma unroll
        for (int nf = 0; nf < 8; nf++) {
            int col = sbase + 8 * nf + 2 * lk;
            int2 mm0 = *(const int2*)(mrow0 + col);
            int2 mm1 = *(const int2*)(mrow1 + col);
            c[nf][0] = mm0.x ? c[nf][0] : NEGBIG;
            c[nf][1] = mm0.y ? c[nf][1] : NEGBIG;
            c[nf][2] = mm1.x ? c[nf][2] : NEGBIG;
            c[nf][3] = mm1.y ? c[nf][3] : NEGBIG;
            mx0 = fmaxf(mx0, fmaxf(c[nf][0], c[nf][1]));
            mx1 = fmaxf(mx1, fmaxf(c[nf][2], c[nf][3]));
        }
        mx0 = fmaxf(mx0, __shfl_xor_sync(0xffffffffu, mx0, 1));
        mx0 = fmaxf(mx0, __shfl_xor_sync(0xffffffffu, mx0, 2));
        mx1 = fmaxf(mx1, __shfl_xor_sync(0xffffffffu, mx1, 1));
        mx1 = fmaxf(mx1, __shfl_xor_sync(0xffffffffu, mx1, 2));
        float m0n = fmaxf(m0, mx0);
        float m1n = fmaxf(m1, mx1);
        float cor0 = __expf(m0 - m0n);
        float cor1 = __expf(m1 - m1n);
        m0 = m0n; m1 = m1n;
        float s0 = 0.f, s1 = 0.f;
        #pragma unroll
        for (int nf = 0; nf < 8; nf++) {
            c[nf][0] = __expf(c[nf][0] - m0);
            c[nf][1] = __expf(c[nf][1] - m0);
            c[nf][2] = __expf(c[nf][2] - m1);
            c[nf][3] = __expf(c[nf][3] - m1);
            s0 += c[nf][0] + c[nf][1];
            s1 += c[nf][2] + c[nf][3];
        }
        s0 += __shfl_xor_sync(0xffffffffu, s0, 1);
        s0 += __shfl_xor_sync(0xffffffffu, s0, 2);
        s1 += __shfl_xor_sync(0xffffffffu, s1, 1);
        s1 += __shfl_xor_sync(0xffffffffu, s1, 2);
        l0 = l0 * cor0 + s0;
        l1 = l1 * cor1 + s1;
        #pragma unroll
        for (int nf = 0; nf < 4; nf++) {
            o[nf][0] *= cor0; o[nf][1] *= cor0;
            o[nf][2] *= cor1; o[nf][3] *= cor1;
        }

        // ---- O += P V (3-pass); P moved C-frag -> A-frag via shuffles ----
        int src0 = 4 * lg + (lk >> 1);
        int src2 = src0 + 2;
        bool odd = (lk & 1) != 0;
        #pragma unroll
        for (int ks = 0; ks < 8; ks++) {
            float t00 = __shfl_sync(0xffffffffu, c[ks][0], src0);
            float t01 = __shfl_sync(0xffffffffu, c[ks][1], src0);
            float t02 = __shfl_sync(0xffffffffu, c[ks][2], src0);
            float t03 = __shfl_sync(0xffffffffu, c[ks][3], src0);
            float t20 = __shfl_sync(0xffffffffu, c[ks][0], src2);
            float t21 = __shfl_sync(0xffffffffu, c[ks][1], src2);
            float t22 = __shfl_sync(0xffffffffu, c[ks][2], src2);
            float t23 = __shfl_sync(0xffffffffu, c[ks][3], src2);
            float a0f = odd ? t01 : t00;   // P[lg   ][8ks+lk  ]
            float a1f = odd ? t03 : t02;   // P[lg+8 ][8ks+lk  ]
            float a2f = odd ? t21 : t20;   // P[lg   ][8ks+lk+4]
            float a3f = odd ? t23 : t22;   // P[lg+8 ][8ks+lk+4]
            float ah[4], al[4];
            split2(a0f, ah[0], al[0]);
            split2(a1f, ah[1], al[1]);
            split2(a2f, ah[2], al[2]);
            split2(a3f, ah[3], al[3]);
            #pragma unroll
            for (int nf = 0; nf < 4; nf++) {
                int n = 8 * nf + lg;
                float bh0 = Vhi[8 * ks + lk][n];
                float bh1 = Vhi[8 * ks + lk + 4][n];
                float bl0 = Vlo[8 * ks + lk][n];
                float bl1 = Vlo[8 * ks + lk + 4][n];
                mma_tf32f(o[nf], ah, bh0, bh1);
                mma_tf32f(o[nf], ah, bl0, bl1);
                mma_tf32f(o[nf], al, bh0, bh1);
            }
        }
        __syncthreads();
    }

    // ---- store partials ----
    size_t pbase = (size_t)(bh * SPLIT2 + sp) * QPAD;
    int r0 = q0 + lg, r1 = q0 + lg + 8;
    if (lk == 0) {
        g_Pm[pbase + r0] = m0;
        g_Pm[pbase + r1] = m1;
        g_Pl[pbase + r0] = l0;
        g_Pl[pbase + r1] = l1;
    }
    #pragma unroll
    for (int nf = 0; nf < 4; nf++) {
        int d = 8 * nf + 2 * lk;
        *(float2*)(g_Pacc + (pbase + r0) * HD + d) = make_float2(o[nf][0], o[nf][1]);
        *(float2*)(g_Pacc + (pbase + r1) * HD + d) = make_float2(o[nf][2], o[nf][3]);
    }
}

// ===========================================================================
// Merge SPLIT2 partials; one warp per (b,h,q), lane = head dim.
// ===========================================================================
__global__ __launch_bounds__(256)
void attn_merge() {
    int warp = (blockIdx.x * blockDim.x + threadIdx.x) >> 5;
    int lane = threadIdx.x & 31;
    if (warp >= BB * HH * QQ) return;
    int bh = warp / QQ, q = warp % QQ;
    int b = bh >> 3, h = bh & 7;
    float M = -INFINITY;
    #pragma unroll
    for (int i = 0; i < SPLIT2; i++)
        M = fmaxf(M, g_Pm[(size_t)(bh * SPLIT2 + i) * QPAD + q]);
    float L = 0.f, ov = 0.f;
    #pragma unroll
    for (int i = 0; i < SPLIT2; i++) {
        size_t idx = (size_t)(bh * SPLIT2 + i) * QPAD + q;
        float w = __expf(g_Pm[idx] - M);
        L += g_Pl[idx] * w;
        ov += g_Pacc[idx * HD + lane] * w;
    }
    g_attn[((size_t)(b * QQ + q)) * EE + h * HD + lane] = ov / L;
}

// ===========================================================================
extern "C" void kernel_launch(void* const* d_in, const int* in_sizes, int n_in,
                              void* d_out, int out_size) {
    const float* query_features = (const float*)d_in[0];
    const float* image_features = (const float*)d_in[1];
    const int*   mask           = (const int*)d_in[2];
    const float* pos_query      = (const float*)d_in[3];
    const float* pos_image      = (const float*)d_in[4];
    const float* Wq = (const float*)d_in[5];
    const float* bq = (const float*)d_in[6];
    const float* Wk = (const float*)d_in[7];
    const float* bk = (const float*)d_in[8];
    const float* Wv = (const float*)d_in[9];
    const float* bv = (const float*)d_in[10];
    const float* Wo = (const float*)d_in[11];
    const float* bo = (const float*)d_in[12];
    float* out = (float*)d_out;

    float* imgT; cudaGetSymbolAddress((void**)&imgT, g_imgT);
    float* Kp;   cudaGetSymbolAddress((void**)&Kp,   g_K);
    float* Vp;   cudaGetSymbolAddress((void**)&Vp,   g_V);
    float* Qp;   cudaGetSymbolAddress((void**)&Qp,   g_Qp);
    float* attn; cudaGetSymbolAddress((void**)&attn, g_attn);

    // 1. transpose image features -> (B*S, E)
    {
        dim3 grid(SS / 32, EE / 32, BB);
        dim3 blk(32, 8);
        transpose_img<<<grid, blk>>>(image_features);
    }
    // 2. Q projection
    {
        int M = BB * QQ;
        dim3 grid((M + 127) / 128, 2);
        mma_gemm<<<grid, 256>>>(query_features, pos_query, Wq, bq, Qp, M);
    }
    // 3. K projection
    {
        dim3 grid((BB * SS) / 128, 2);
        mma_gemm<<<grid, 256>>>(imgT, pos_image, Wk, bk, Kp, BB * SS);
    }
    // 4. V projection
    {
        dim3 grid((BB * SS) / 128, 2);
        mma_gemm<<<grid, 256>>>(imgT, nullptr, Wv, bv, Vp, BB * SS);
    }
    // 5. attention partials (tensor-core flash)
    {
        dim3 grid(BB * HH, SPLIT2);
        attn_mma<<<grid, 256>>>(mask);
    }
    // 6. merge partials
    {
        int nthreads = BB * HH * QQ * 32;
        attn_merge<<<(nthreads + 255) / 256, 256>>>();
    }
    // 7. output projection
    {
        int M = BB * QQ;
        dim3 grid((M + 127) / 128, 2);
        mma_gemm<<<grid, 256>>>(attn, nullptr, Wo, bo, out, M);
    }
}